// round 9
// baseline (speedup 1.0000x reference)
#include <cuda_runtime.h>
#include <cstdint>

typedef unsigned long long u64;

#define BB   256
#define TT   2048
#define HH   256
#define PP   24
#define BC   2              // batch rows per CTA
#define NCTA (BB/BC)        // 128
#define NTHR 256            // 8 warps; each thread: 8 rows x 32 cols
#define NSMC 16             // W float4-chunks in smem per thread (rows 6,7)

// packed f32x2 FMA: d = a*b + d
__device__ __forceinline__ void fma2(u64 &d, u64 a, u64 b) {
    asm("fma.rn.f32x2 %0, %1, %2, %0;" : "+l"(d) : "l"(a), "l"(b));
}
__device__ __forceinline__ float2 unpk(u64 v) {
    float2 r; asm("mov.b64 {%0, %1}, %2;" : "=f"(r.x), "=f"(r.y) : "l"(v)); return r;
}

// SMEM layout:
//  [0, 64K)     sW[c][t] : W chunk c of thread t (ulonglong2), c < NSMC (rows 6,7)
//  [64K, 68K)   h double buffer [2][BC][HH] floats (XOR-swizzled, see hword)
//  [68K, 84K)   x stage [BC][TT]
#define SW_BYTES   ((size_t)NSMC * NTHR * 16)
#define HB_BYTES   ((size_t)2 * BC * HH * 4)
#define X_BYTES    ((size_t)BC * TT * 4)
#define SMEM_TOTAL (SW_BYTES + HB_BYTES + X_BYTES)

// storage word (within one 512-float h buffer) for (col, batch):
//   c=(col>>2)&7, kk=col>>5, j=col&3 ; float4 idx = c*8 + (kk^c)
// Reads (fixed c, lanes k=0..7): 8 distinct float4 in an 8-aligned block -> 1 wavefront.
// Writes (warp: rows 8g+k): 32 distinct banks -> 1 wavefront.
__device__ __forceinline__ int hword(int col, int b) {
    int c = (col >> 2) & 7, kk = col >> 5, j = col & 3;
    return b * HH + ((((c << 3) | (kk ^ c)) << 2) | j);
}

// fast tanh: 1 - 2/(e^{2x}+1). |err| ~1e-7 rel, branch-free, inf-safe.
__device__ __forceinline__ float ftanh(float x) {
    float e = __expf(x + x);
    return 1.0f - __fdividef(2.0f, e + 1.0f);
}

__global__ void __launch_bounds__(NTHR, 1)
rnn_persistent_kernel(const float* __restrict__ x,
                      const float* __restrict__ W_ih,
                      const float* __restrict__ W_hh,
                      const float* __restrict__ b_ih,
                      const float* __restrict__ b_hh,
                      const float* __restrict__ W_out,
                      const float* __restrict__ b_out,
                      float* __restrict__ out)
{
    extern __shared__ char smem[];
    ulonglong2* sW   = (ulonglong2*)smem;
    float*      hbuf = (float*)(smem + SW_BYTES);
    float*      sx   = (float*)(smem + SW_BYTES + HB_BYTES);

    const int t  = threadIdx.x;
    const int g  = t >> 3;      // row group: rows 8g..8g+7
    const int k  = t & 7;       // column strip: cols 32k..32k+31
    const int b0 = blockIdx.x * BC;

    // ---- Prologue: thread (g,k) owns rows 8g+j (j<8), row-local float4 idx k*8+c.
    // Rows 0..5 -> registers (48 float4 = 192 regs). Rows 6,7 -> smem.
    const ulonglong2* Wv = (const ulonglong2*)W_hh;   // row stride = 64 float4
    ulonglong2 wr[48];
#pragma unroll
    for (int j = 0; j < 6; j++)
#pragma unroll
        for (int c = 0; c < 8; c++)
            wr[j*8 + c] = Wv[(size_t)(8*g + j) * 64 + k*8 + c];
#pragma unroll
    for (int j = 0; j < 2; j++)
#pragma unroll
        for (int c = 0; c < 8; c++)
            sW[(j*8 + c) * NTHR + t] = Wv[(size_t)(8*g + 6 + j) * 64 + k*8 + c];

    // lane-owned outputs after reduction: row 8g+k, both batches
    const int myrow  = 8*g + k;
    const float bias = b_ih[myrow] + b_hh[myrow];
    const float wih  = W_ih[myrow];
    const int wpos0  = hword(myrow, 0);
    const int wpos1  = hword(myrow, 1);

    // stage x[b0:b0+BC, :] into smem (coalesced float4)
    {
        const float4* xg = (const float4*)(x + (size_t)b0 * TT);
        float4*       xs = (float4*)sx;
#pragma unroll
        for (int q = t; q < BC * TT / 4; q += NTHR) xs[q] = xg[q];
    }
    hbuf[t] = 0.0f; hbuf[NTHR + t] = 0.0f;   // zero h buffer 0
    __syncthreads();

    const bool sel4 = (k & 4) != 0;
    const bool sel2 = (k & 2) != 0;
    const bool sel1 = (k & 1) != 0;

    int rb = 0;
    for (int ts = 0; ts < TT; ts++) {
        const ulonglong2* hr = (const ulonglong2*)(hbuf + rb * (BC * HH));

        // hoisted input projection (independent of h -> off the tail's critical path)
        const float pre0b = fmaf(sx[ts],      wih, bias);
        const float pre1b = fmaf(sx[TT + ts], wih, bias);

        // ---- Pass A: smem rows 6,7 (issues the long-latency W LDS burst first)
        u64 B0 = 0ull, B1 = 0ull, B2 = 0ull, B3 = 0ull;  // (j6,b0)(j6,b1)(j7,b0)(j7,b1)
#pragma unroll
        for (int c = 0; c < 8; c++) {
            const int m0 = k ^ c;
            ulonglong2 h0 = hr[c*8 + m0];
            ulonglong2 h1 = hr[64 + c*8 + m0];
            ulonglong2 w6 = sW[c * NTHR + t];
            ulonglong2 w7 = sW[(8 + c) * NTHR + t];
            fma2(B0, h0.x, w6.x); fma2(B0, h0.y, w6.y);
            fma2(B1, h1.x, w6.x); fma2(B1, h1.y, w6.y);
            fma2(B2, h0.x, w7.x); fma2(B2, h0.y, w7.y);
            fma2(B3, h1.x, w7.x); fma2(B3, h1.y, w7.y);
        }
        float sB0, sB1, sB2, sB3;
        { float2 f = unpk(B0); sB0 = f.x + f.y; }
        { float2 f = unpk(B1); sB1 = f.x + f.y; }
        { float2 f = unpk(B2); sB2 = f.x + f.y; }
        { float2 f = unpk(B3); sB3 = f.x + f.y; }

        // ---- Pass B: register rows 0..5
        u64 A[12];   // A[j*2+b], j<6
#pragma unroll
        for (int m = 0; m < 12; m++) A[m] = 0ull;
#pragma unroll
        for (int c = 0; c < 8; c++) {
            const int m0 = k ^ c;
            ulonglong2 h0 = hr[c*8 + m0];
            ulonglong2 h1 = hr[64 + c*8 + m0];
#pragma unroll
            for (int j = 0; j < 6; j++) {
                ulonglong2 w = wr[j*8 + c];
                fma2(A[j*2],   h0.x, w.x); fma2(A[j*2],   h0.y, w.y);
                fma2(A[j*2+1], h1.x, w.x); fma2(A[j*2+1], h1.y, w.y);
            }
        }

        float s[16];
#pragma unroll
        for (int m = 0; m < 12; m++) { float2 f = unpk(A[m]); s[m] = f.x + f.y; }
        s[12] = sB0; s[13] = sB1; s[14] = sB2; s[15] = sB3;

        // 8-lane tree reduction; lane k ends with row 8g+k, both batches.
        float r8[8];
#pragma unroll
        for (int q = 0; q < 8; q++) {
            float keep = sel4 ? s[q + 8] : s[q];
            float send = sel4 ? s[q] : s[q + 8];
            r8[q] = keep + __shfl_xor_sync(0xffffffffu, send, 4);
        }
        float r4[4];
#pragma unroll
        for (int q = 0; q < 4; q++) {
            float keep = sel2 ? r8[q + 4] : r8[q];
            float send = sel2 ? r8[q] : r8[q + 4];
            r4[q] = keep + __shfl_xor_sync(0xffffffffu, send, 2);
        }
        float v0, v1;
        {
            float keep0 = sel1 ? r4[2] : r4[0], send0 = sel1 ? r4[0] : r4[2];
            float keep1 = sel1 ? r4[3] : r4[1], send1 = sel1 ? r4[1] : r4[3];
            v0 = keep0 + __shfl_xor_sync(0xffffffffu, send0, 1);
            v1 = keep1 + __shfl_xor_sync(0xffffffffu, send1, 1);
        }

        const int wo = (rb ^ 1) * (BC * HH);
        hbuf[wo + wpos0] = ftanh(v0 + pre0b);
        hbuf[wo + wpos1] = ftanh(v1 + pre1b);
        __syncthreads();
        rb ^= 1;
    }

    // ---- Epilogue: out[b,p] = h_T[b,:] . W_out[p,:] + b_out[p]  (h in buf 0)
    if (t < BC * PP) {
        const int bb = t / PP;
        const int p  = t % PP;
        const float* wo = W_out + (size_t)p * HH;
        float acc = b_out[p];
#pragma unroll 8
        for (int col = 0; col < HH; col++)
            acc = fmaf(hbuf[hword(col, bb)], wo[col], acc);
        out[(size_t)(b0 + bb) * PP + p] = acc;
    }
}

extern "C" void kernel_launch(void* const* d_in, const int* in_sizes, int n_in,
                              void* d_out, int out_size)
{
    const float* x     = (const float*)d_in[0];
    const float* W_ih  = (const float*)d_in[1];
    const float* W_hh  = (const float*)d_in[2];
    const float* b_ih  = (const float*)d_in[3];
    const float* b_hh  = (const float*)d_in[4];
    const float* W_out = (const float*)d_in[5];
    const float* b_out = (const float*)d_in[6];
    float* out = (float*)d_out;

    cudaFuncSetAttribute(rnn_persistent_kernel,
                         cudaFuncAttributeMaxDynamicSharedMemorySize, (int)SMEM_TOTAL);
    rnn_persistent_kernel<<<NCTA, NTHR, SMEM_TOTAL>>>(x, W_ih, W_hh, b_ih, b_hh,
                                                      W_out, b_out, out);
}

// round 10
// speedup vs baseline: 1.1381x; 1.1381x over previous
#include <cuda_runtime.h>
#include <cstdint>

typedef unsigned long long u64;

#define BB   256
#define TT   2048
#define HH   256
#define PP   24
#define BC   2              // batch rows per CTA
#define NCTA (BB/BC)        // 128
#define NTHR 256            // 8 warps; each thread: 8 rows x 32 cols
#define NSMC 24             // W float4-chunks in smem per thread (slots 5,6,7)

// packed f32x2 ops
__device__ __forceinline__ void fma2(u64 &d, u64 a, u64 b) {
    asm("fma.rn.f32x2 %0, %1, %2, %0;" : "+l"(d) : "l"(a), "l"(b));
}
__device__ __forceinline__ void mul2(u64 &d, u64 a, u64 b) {
    asm("mul.rn.f32x2 %0, %1, %2;" : "=l"(d) : "l"(a), "l"(b));
}
__device__ __forceinline__ float2 unpk(u64 v) {
    float2 r; asm("mov.b64 {%0, %1}, %2;" : "=f"(r.x), "=f"(r.y) : "l"(v)); return r;
}

// SMEM layout:
//  [0, 96K)     sW[c][t] : W chunk c of thread t (ulonglong2), c < NSMC
//  [96K,100K)   h double buffer [2][BC][HH] floats (XOR-swizzled, see hword)
//  [100K,116K)  x stage [BC][TT]
#define SW_BYTES   ((size_t)NSMC * NTHR * 16)
#define HB_BYTES   ((size_t)2 * BC * HH * 4)
#define X_BYTES    ((size_t)BC * TT * 4)
#define SMEM_TOTAL (SW_BYTES + HB_BYTES + X_BYTES)

// storage word (within one 512-float h buffer) for (col, batch):
//   c=(col>>2)&7, kk=col>>5, j=col&3 ; float4 idx = c*8 + (kk^c)
// Reads (fixed c, lanes k=0..7): 8 distinct float4 in an 8-aligned block -> 1 wavefront.
// Writes (warp: rows 8g+k): 32 distinct banks -> 1 wavefront.
__device__ __forceinline__ int hword(int col, int b) {
    int c = (col >> 2) & 7, kk = col >> 5, j = col & 3;
    return b * HH + ((((c << 3) | (kk ^ c)) << 2) | j);
}

// fast tanh: 1 - 2/(e^{2x}+1). branch-free, inf-safe.
__device__ __forceinline__ float ftanh(float x) {
    float e = __expf(x + x);
    return 1.0f - __fdividef(2.0f, e + 1.0f);
}

__global__ void __launch_bounds__(NTHR, 1)
rnn_persistent_kernel(const float* __restrict__ x,
                      const float* __restrict__ W_ih,
                      const float* __restrict__ W_hh,
                      const float* __restrict__ b_ih,
                      const float* __restrict__ b_hh,
                      const float* __restrict__ W_out,
                      const float* __restrict__ b_out,
                      float* __restrict__ out)
{
    extern __shared__ char smem[];
    ulonglong2* sW   = (ulonglong2*)smem;
    float*      hbuf = (float*)(smem + SW_BYTES);
    float*      sx   = (float*)(smem + SW_BYTES + HB_BYTES);

    const int t  = threadIdx.x;
    const int g  = t >> 3;      // row group: rows 8g..8g+7
    const int k  = t & 7;       // column strip: cols 32k..32k+31
    const int b0 = blockIdx.x * BC;

    // ---- Prologue.
    // Slot-swizzle: physical slot jp holds logical row (jp ^ k). This makes the
    // shfl reduction tree select-free; lane k still ends owning row 8g+k.
    // Slots 0..4 -> registers (40 float4 = 160 regs). Slots 5,6,7 -> smem.
    const ulonglong2* Wv = (const ulonglong2*)W_hh;   // row stride = 64 float4
    ulonglong2 wr[40];
#pragma unroll
    for (int jp = 0; jp < 5; jp++)
#pragma unroll
        for (int c = 0; c < 8; c++)
            wr[jp*8 + c] = Wv[(size_t)(8*g + (jp ^ k)) * 64 + k*8 + c];
#pragma unroll
    for (int jp = 0; jp < 3; jp++)
#pragma unroll
        for (int c = 0; c < 8; c++)
            sW[(jp*8 + c) * NTHR + t] = Wv[(size_t)(8*g + ((5 + jp) ^ k)) * 64 + k*8 + c];

    // lane-owned outputs after reduction: row 8g+k, both batches
    const int myrow  = 8*g + k;
    const float bias = b_ih[myrow] + b_hh[myrow];
    const float wih  = W_ih[myrow];
    const int wpos0  = hword(myrow, 0);
    const int wpos1  = hword(myrow, 1);

    // stage x[b0:b0+BC, :] into smem (coalesced float4)
    {
        const float4* xg = (const float4*)(x + (size_t)b0 * TT);
        float4*       xs = (float4*)sx;
#pragma unroll
        for (int q = t; q < BC * TT / 4; q += NTHR) xs[q] = xg[q];
    }
    hbuf[t] = 0.0f; hbuf[NTHR + t] = 0.0f;   // zero h buffer 0
    __syncthreads();

    int rb = 0;
    for (int ts = 0; ts < TT; ts++) {
        const ulonglong2* hr = (const ulonglong2*)(hbuf + rb * (BC * HH));

        // hoisted input projection (h-independent, off the tail critical path)
        const float pre0b = fmaf(sx[ts],      wih, bias);
        const float pre1b = fmaf(sx[TT + ts], wih, bias);

        u64 A[16];   // A[jp*2 + b] : partial for logical row (jp^k)
#pragma unroll
        for (int c = 0; c < 8; c++) {
            const int m0 = k ^ c;
            ulonglong2 h0 = hr[c*8 + m0];
            ulonglong2 h1 = hr[64 + c*8 + m0];
            ulonglong2 w5 = sW[c * NTHR + t];
            ulonglong2 w6 = sW[(8 + c) * NTHR + t];
            ulonglong2 w7 = sW[(16 + c) * NTHR + t];
            if (c == 0) {
#pragma unroll
                for (int jp = 0; jp < 5; jp++) {
                    ulonglong2 w = wr[jp*8];
                    mul2(A[jp*2],   h0.x, w.x); fma2(A[jp*2],   h0.y, w.y);
                    mul2(A[jp*2+1], h1.x, w.x); fma2(A[jp*2+1], h1.y, w.y);
                }
                mul2(A[10], h0.x, w5.x); fma2(A[10], h0.y, w5.y);
                mul2(A[11], h1.x, w5.x); fma2(A[11], h1.y, w5.y);
                mul2(A[12], h0.x, w6.x); fma2(A[12], h0.y, w6.y);
                mul2(A[13], h1.x, w6.x); fma2(A[13], h1.y, w6.y);
                mul2(A[14], h0.x, w7.x); fma2(A[14], h0.y, w7.y);
                mul2(A[15], h1.x, w7.x); fma2(A[15], h1.y, w7.y);
            } else {
#pragma unroll
                for (int jp = 0; jp < 5; jp++) {
                    ulonglong2 w = wr[jp*8 + c];
                    fma2(A[jp*2],   h0.x, w.x); fma2(A[jp*2],   h0.y, w.y);
                    fma2(A[jp*2+1], h1.x, w.x); fma2(A[jp*2+1], h1.y, w.y);
                }
                fma2(A[10], h0.x, w5.x); fma2(A[10], h0.y, w5.y);
                fma2(A[11], h1.x, w5.x); fma2(A[11], h1.y, w5.y);
                fma2(A[12], h0.x, w6.x); fma2(A[12], h0.y, w6.y);
                fma2(A[13], h1.x, w6.x); fma2(A[13], h1.y, w6.y);
                fma2(A[14], h0.x, w7.x); fma2(A[14], h0.y, w7.y);
                fma2(A[15], h1.x, w7.x); fma2(A[15], h1.y, w7.y);
            }
        }

        float s[16];
#pragma unroll
        for (int m = 0; m < 16; m++) { float2 f = unpk(A[m]); s[m] = f.x + f.y; }

        // Select-free tree: slot-swizzled accumulators mean every lane keeps the
        // low half and receives the partner's high half at each level.
        float r8[8];
#pragma unroll
        for (int q = 0; q < 8; q++)
            r8[q] = s[q] + __shfl_xor_sync(0xffffffffu, s[q + 8], 4);
        float r4[4];
#pragma unroll
        for (int q = 0; q < 4; q++)
            r4[q] = r8[q] + __shfl_xor_sync(0xffffffffu, r8[q + 4], 2);
        float v0 = r4[0] + __shfl_xor_sync(0xffffffffu, r4[2], 1);
        float v1 = r4[1] + __shfl_xor_sync(0xffffffffu, r4[3], 1);

        const int wo = (rb ^ 1) * (BC * HH);
        hbuf[wo + wpos0] = ftanh(v0 + pre0b);
        hbuf[wo + wpos1] = ftanh(v1 + pre1b);
        __syncthreads();
        rb ^= 1;
    }

    // ---- Epilogue: out[b,p] = h_T[b,:] . W_out[p,:] + b_out[p]  (h in buf 0)
    if (t < BC * PP) {
        const int bb = t / PP;
        const int p  = t % PP;
        const float* wo = W_out + (size_t)p * HH;
        float acc = b_out[p];
#pragma unroll 8
        for (int col = 0; col < HH; col++)
            acc = fmaf(hbuf[hword(col, bb)], wo[col], acc);
        out[(size_t)(b0 + bb) * PP + p] = acc;
    }
}

extern "C" void kernel_launch(void* const* d_in, const int* in_sizes, int n_in,
                              void* d_out, int out_size)
{
    const float* x     = (const float*)d_in[0];
    const float* W_ih  = (const float*)d_in[1];
    const float* W_hh  = (const float*)d_in[2];
    const float* b_ih  = (const float*)d_in[3];
    const float* b_hh  = (const float*)d_in[4];
    const float* W_out = (const float*)d_in[5];
    const float* b_out = (const float*)d_in[6];
    float* out = (float*)d_out;

    cudaFuncSetAttribute(rnn_persistent_kernel,
                         cudaFuncAttributeMaxDynamicSharedMemorySize, (int)SMEM_TOTAL);
    rnn_persistent_kernel<<<NCTA, NTHR, SMEM_TOTAL>>>(x, W_ih, W_hh, b_ih, b_hh,
                                                      W_out, b_out, out);
}